// round 9
// baseline (speedup 1.0000x reference)
#include <cuda_runtime.h>
#include <cuda_bf16.h>
#include <cstdint>

typedef unsigned short u16;
typedef unsigned int u32;

#define BATCH 32
#define SEQ   2048
#define STATE 64
#define LAT   128
#define ENC   256
#define IND   320
#define NPOS  (BATCH*SEQ)
#define NCHUNK 64
#define CLEN   32
#define RPC    8
#define NBS    4

// ---------------- device scratch ----------------
__device__ float g_sum[LAT];
__device__ float g_sumsq[LAT];
__device__ float g_z0[BATCH*LAT];
__device__ float g_h0[BATCH*LAT];
__device__ float g_Ap0[LAT*LAT];
__device__ float g_Ap1[LAT*LAT];
__device__ float g_lend[NCHUNK*BATCH*LAT];
__device__ float g_sk[NCHUNK*BATCH*LAT];
__device__ u16 g_a1h[(size_t)NPOS*ENC], g_a1l[(size_t)NPOS*ENC];
__device__ u16 g_a2h[(size_t)NPOS*ENC], g_a2l[(size_t)NPOS*ENC];
__device__ u16 g_z1h[(size_t)NPOS*LAT], g_z1l[(size_t)NPOS*LAT];
__device__ __align__(16) u16 g_we0h[256*1*72], g_we0l[256*1*72];
__device__ __align__(16) u16 g_we1h[256*4*72], g_we1l[256*4*72];
__device__ __align__(16) u16 g_we2h[128*4*72], g_we2l[128*4*72];
__device__ __align__(16) u16 g_wd0h[256*2*72], g_wd0l[256*2*72];
__device__ __align__(16) u16 g_wd1h[256*4*72], g_wd1l[256*4*72];
__device__ __align__(16) u16 g_wd2h[64*4*72],  g_wd2l[64*4*72];

// ---------------- helpers ----------------
__device__ __forceinline__ u32 smem_u32(const void* p) {
    u32 a;
    asm("{ .reg .u64 t; cvta.to.shared.u64 t, %1; cvt.u32.u64 %0, t; }" : "=r"(a) : "l"(p));
    return a;
}
#define LDSM4(r, a) \
    asm volatile("ldmatrix.sync.aligned.m8n8.x4.shared.b16 {%0,%1,%2,%3}, [%4];" \
        : "=r"((r)[0]), "=r"((r)[1]), "=r"((r)[2]), "=r"((r)[3]) : "r"(a))
#define MMA(d, a, b) \
    asm volatile("mma.sync.aligned.m16n8k16.row.col.f32.bf16.bf16.f32 " \
        "{%0,%1,%2,%3},{%4,%5,%6,%7},{%8,%9},{%0,%1,%2,%3};" \
        : "+f"((d)[0]), "+f"((d)[1]), "+f"((d)[2]), "+f"((d)[3]) \
        : "r"((a)[0]), "r"((a)[1]), "r"((a)[2]), "r"((a)[3]), "r"((b)[0]), "r"((b)[1]))
#define CPA16(dst, src) asm volatile("cp.async.cg.shared.global [%0], [%1], 16;" :: "r"(dst), "l"(src))
#define CPA_COMMIT()  asm volatile("cp.async.commit_group;" ::: "memory")
#define CPA_WAIT0()   asm volatile("cp.async.wait_group 0;" ::: "memory")
#define CPA_WAIT1()   asm volatile("cp.async.wait_group 1;" ::: "memory")

__device__ __forceinline__ u16 bfh(float v) {
    __nv_bfloat16 b = __float2bfloat16(v);
    return *(u16*)&b;
}
__device__ __forceinline__ void split2(float v, u16& h, u16& l) {
    __nv_bfloat16 b = __float2bfloat16(v);
    h = *(u16*)&b;
    l = bfh(v - __bfloat162float(b));
}

// ---------------- small kernels ----------------
__global__ void k_init() {
    int t = threadIdx.x;
    if (t < LAT) { g_sum[t] = 0.f; g_sumsq[t] = 0.f; }
}

__global__ void k_sq(const float* __restrict__ Aw, int step) {
    extern __shared__ float S[];
    const float* src = (step == 0) ? Aw : ((step & 1) ? g_Ap0 : g_Ap1);
    float* dst = (step & 1) ? g_Ap1 : g_Ap0;
    int t = threadIdx.x;
    for (int i = t; i < LAT*LAT; i += 512) S[i] = src[i];
    __syncthreads();
    int base = blockIdx.x * 512 + t;
    int i = base >> 7, j = base & 127;
    float acc = 0.f;
#pragma unroll 8
    for (int k = 0; k < LAT; k++) acc = fmaf(S[i*LAT + k], S[k*LAT + j], acc);
    dst[base] = acc;
}

__global__ void k_prepw(const float* __restrict__ W, int K, int N, int NT,
                        u16* __restrict__ oh, u16* __restrict__ ol) {
    int idx = blockIdx.x * 256 + threadIdx.x;
    if (idx >= K * N) return;
    int k = idx / N, n = idx % N;
    int NCH = K >> 6;
    int nt = n / NT, nloc = n % NT, c = k >> 6, kl = k & 63;
    u16 h, l;
    split2(W[idx], h, l);
    size_t d = ((size_t)(nt * NCH + c) * NT + nloc) * 72 + kl;
    oh[d] = h; ol[d] = l;
}

// ---------------- HMMA GEMM (double-buffered pipeline when NCH>1) ----------------
template<int K, int NT, int EPI, int ASRC>
__global__ void __launch_bounds__(256, 2) k_gemm(
    const float* __restrict__ A32, const u16* __restrict__ Ah, const u16* __restrict__ Al, int lda,
    const u16* __restrict__ Wh, const u16* __restrict__ Wl,
    const float* __restrict__ bias,
    u16* __restrict__ Oh, u16* __restrict__ Ol, float* __restrict__ outF, int ldo)
{
    constexpr int KC  = 64;
    constexpr int NCH = K / KC;
    constexpr int ST  = (NCH > 1) ? 2 : 1;   // pipeline stages
    constexpr int SMA = 128 * 144;
    constexpr int SMW = NT * 144;
    constexpr int ABLK = ST * SMA;
    constexpr int WBLK = ST * SMW;
    constexpr int SB  = 2*ABLK + 2*WBLK;
    constexpr int MT  = (NT == 128) ? 2 : 1;
    constexpr int WM  = (NT == 128) ? 4 : 8;

    extern __shared__ char sm[];
    u32 sb = smem_u32(sm);
    int tid = threadIdx.x, wid = tid >> 5, l = tid & 31;
    int wm = wid % WM, wn = wid / WM;
    int tile = blockIdx.x, nt = blockIdx.y, nt0 = nt * NT;
    int RW = wm * (MT * 16);

    float* sbias = (float*)(sm + SB);
    float* ssum  = (float*)(sm + SB + 512);
    float* ssq   = (float*)(sm + SB + 1024);
    if (tid < NT) sbias[tid] = bias[nt0 + tid];
    if (EPI == 1 && tid < 128) { ssum[tid] = 0.f; ssq[tid] = 0.f; }

    float acc[MT][8][4];
#pragma unroll
    for (int mt = 0; mt < MT; mt++)
#pragma unroll
        for (int n = 0; n < 8; n++)
#pragma unroll
            for (int i = 0; i < 4; i++) acc[mt][n][i] = 0.f;

    u32 aoff = (RW + (l & 15)) * 144 + (l >> 4) * 16;
    u32 boff = (wn*64 + (l & 7) + ((l >> 4) * 8)) * 144 + (((l >> 3) & 1) * 16);

    // stage bases
    auto baseAh = [&](int s){ return sb + s*SMA; };
    auto baseAl = [&](int s){ return sb + ABLK + s*SMA; };
    auto baseWh = [&](int s){ return sb + 2*ABLK + s*SMW; };
    auto baseWl = [&](int s){ return sb + 2*ABLK + WBLK + s*SMW; };

    // async load of chunk c into stage s (W always; A if ASRC==1)
    auto load_chunk = [&](int c, int s) {
        const u16* wh = Wh + (size_t)(nt * NCH + c) * NT * 72;
        const u16* wl = Wl + (size_t)(nt * NCH + c) * NT * 72;
        u32 bWh = baseWh(s), bWl = baseWl(s);
#pragma unroll
        for (int i = tid; i < NT * 9; i += 256) {
            CPA16(bWh + i*16, wh + i*8);
            CPA16(bWl + i*16, wl + i*8);
        }
        if (ASRC == 1) {
            u32 bAh = baseAh(s), bAl = baseAl(s);
#pragma unroll
            for (int i = tid; i < 1024; i += 256) {
                int row = i >> 3, seg = i & 7;
                size_t go = (size_t)(tile*128 + row) * lda + c*KC + seg*8;
                u32 d = row*144 + seg*16;
                CPA16(bAh + d, Ah + go);
                CPA16(bAl + d, Al + go);
            }
        }
    };

    // prologue
    load_chunk(0, 0);
    if (ASRC == 0) {   // enc L0: register split of fp32 A (single chunk)
        int r = tid & 127, kh = (tid >> 7) * 32;
        const float* ap = A32 + (size_t)(tile*128 + r) * lda + kh;
#pragma unroll
        for (int j = 0; j < 4; j++) {
            float4 f0 = *(const float4*)(ap + j*8);
            float4 f1 = *(const float4*)(ap + j*8 + 4);
            float f[8] = {f0.x,f0.y,f0.z,f0.w,f1.x,f1.y,f1.z,f1.w};
            union { u16 us[8]; uint4 u; } ph, pl;
#pragma unroll
            for (int q = 0; q < 8; q++) split2(f[q], ph.us[q], pl.us[q]);
            int off = r*144 + (kh + j*8)*2;
            *(uint4*)(sm + off)            = ph.u;
            *(uint4*)(sm + ABLK + off)     = pl.u;
        }
    }
    CPA_COMMIT();

    for (int c = 0; c < NCH; c++) {
        int s = c & (ST - 1);
        if (ST == 2 && c + 1 < NCH) { load_chunk(c + 1, (c + 1) & 1); CPA_COMMIT(); }
        if (ST == 2 && c + 1 < NCH) CPA_WAIT1(); else CPA_WAIT0();
        __syncthreads();

        u32 sAh = baseAh(s), sAl = baseAl(s), sWh = baseWh(s), sWl = baseWl(s);
#pragma unroll
        for (int ks = 0; ks < 4; ks++) {
            int k2 = ks * 32;
            u32 ah[MT][4], al[MT][4], bf[4][4];
#pragma unroll
            for (int mt = 0; mt < MT; mt++) LDSM4(ah[mt], sAh + aoff + mt*2304 + k2);
#pragma unroll
            for (int mt = 0; mt < MT; mt++) LDSM4(al[mt], sAl + aoff + mt*2304 + k2);
#pragma unroll
            for (int p = 0; p < 4; p++)     LDSM4(bf[p], sWh + boff + p*2304 + k2);
#pragma unroll
            for (int mt = 0; mt < MT; mt++)
#pragma unroll
                for (int p = 0; p < 4; p++) {
                    MMA(acc[mt][2*p],   ah[mt], bf[p]);
                    MMA(acc[mt][2*p+1], ah[mt], &bf[p][2]);
                }
#pragma unroll
            for (int mt = 0; mt < MT; mt++)
#pragma unroll
                for (int p = 0; p < 4; p++) {
                    MMA(acc[mt][2*p],   al[mt], bf[p]);
                    MMA(acc[mt][2*p+1], al[mt], &bf[p][2]);
                }
#pragma unroll
            for (int p = 0; p < 4; p++)     LDSM4(bf[p], sWl + boff + p*2304 + k2);
#pragma unroll
            for (int mt = 0; mt < MT; mt++)
#pragma unroll
                for (int p = 0; p < 4; p++) {
                    MMA(acc[mt][2*p],   ah[mt], bf[p]);
                    MMA(acc[mt][2*p+1], ah[mt], &bf[p][2]);
                }
        }
        __syncthreads();
    }

    int g = l >> 2, tg = l & 3;
#pragma unroll
    for (int mt = 0; mt < MT; mt++) {
        int row = tile*128 + RW + mt*16 + g;
#pragma unroll
        for (int n = 0; n < 8; n++) {
            int colL = wn*64 + n*8 + tg*2;
            float b0 = sbias[colL], b1 = sbias[colL + 1];
            float v0 = acc[mt][n][0] + b0, v1 = acc[mt][n][1] + b1;
            float v2 = acc[mt][n][2] + b0, v3 = acc[mt][n][3] + b1;
            if (EPI != 2) {
                v0 = fmaxf(v0, 0.f); v1 = fmaxf(v1, 0.f);
                v2 = fmaxf(v2, 0.f); v3 = fmaxf(v3, 0.f);
            }
            if (EPI == 1) {
                atomicAdd(&ssum[colL],     v0 + v2);
                atomicAdd(&ssq[colL],      v0*v0 + v2*v2);
                atomicAdd(&ssum[colL + 1], v1 + v3);
                atomicAdd(&ssq[colL + 1],  v1*v1 + v3*v3);
                if (((tile & 15) == 0) && g == 0 && wm == 0 && mt == 0) {
                    g_z0[(tile >> 4) * LAT + colL]     = v0;
                    g_z0[(tile >> 4) * LAT + colL + 1] = v1;
                }
            } else if (EPI == 0) {
                u16 h0,l0,h1,l1,h2,l2,h3,l3;
                split2(v0,h0,l0); split2(v1,h1,l1); split2(v2,h2,l2); split2(v3,h3,l3);
                size_t o0 = (size_t)row * ldo + nt0 + colL;
                size_t o1 = (size_t)(row + 8) * ldo + nt0 + colL;
                *(u32*)&Oh[o0] = (u32)h0 | ((u32)h1 << 16);
                *(u32*)&Ol[o0] = (u32)l0 | ((u32)l1 << 16);
                *(u32*)&Oh[o1] = (u32)h2 | ((u32)h3 << 16);
                *(u32*)&Ol[o1] = (u32)l2 | ((u32)l3 << 16);
            } else {
                *(float2*)&outF[(size_t)row * ldo + nt0 + colL]       = make_float2(v0, v1);
                *(float2*)&outF[(size_t)(row + 8) * ldo + nt0 + colL] = make_float2(v2, v3);
            }
        }
    }
    if (EPI == 1) {
        __syncthreads();
        if (tid < 128) {
            atomicAdd(&g_sum[tid],   ssum[tid]);
            atomicAdd(&g_sumsq[tid], ssq[tid]);
        }
    }
}

// ---------------- BN finalize ----------------
__global__ void k_fin(const float* __restrict__ gamma, const float* __restrict__ beta)
{
    int j = threadIdx.x;
    float inv = 1.f / (float)NPOS;
    float m  = g_sum[j] * inv;
    float v  = g_sumsq[j] * inv - m * m;
    float rs = rsqrtf(v + 1e-5f);
    float ga = gamma[j], be = beta[j];
    for (int b = 0; b < BATCH; b++) {
        float z = g_z0[b*LAT + j];
        g_h0[b*LAT + j] = (z - m) * rs * ga + be;
    }
}

// ---------------- chunked scan ----------------
__global__ void __launch_bounds__(128) k_pass(const float* __restrict__ in,
                                              const float* __restrict__ Aw,
                                              const float* __restrict__ Bd, int pass)
{
    extern __shared__ float smf[];
    float* As = smf;
    float* hs = smf + LAT * LAT;
    int j     = threadIdx.x;
    int chunk = blockIdx.x;
    int b0r   = blockIdx.y * RPC;

    for (int idx = j; idx < LAT * LAT; idx += 128) As[idx] = Aw[idx];
    float dj = fminf(fmaxf(Bd[j], -0.95f), 0.95f);
#pragma unroll
    for (int i = 0; i < RPC; i++) {
        float v = (pass == 0) ? 0.f : g_sk[(chunk * BATCH + (b0r + i)) * LAT + j];
        hs[i * LAT + j] = v;
    }
    __syncthreads();

    int t0 = chunk * CLEN;
    int buf = 0;
    for (int t = t0; t < t0 + CLEN; t++) {
        float acc[RPC];
#pragma unroll
        for (int i = 0; i < RPC; i++)
            acc[i] = in[((long)(b0r + i) * SEQ + t) * IND + (STATE + LAT) + j] * dj;

        const float* hb = hs + buf * (RPC * LAT);
#pragma unroll 8
        for (int k4 = 0; k4 < LAT; k4 += 4) {
            float a0 = As[(k4+0)*LAT + j], a1 = As[(k4+1)*LAT + j];
            float a2 = As[(k4+2)*LAT + j], a3 = As[(k4+3)*LAT + j];
#pragma unroll
            for (int i = 0; i < RPC; i++) {
                float4 h = *(const float4*)&hb[i * LAT + k4];
                acc[i] = fmaf(h.x, a0, fmaf(h.y, a1, fmaf(h.z, a2, fmaf(h.w, a3, acc[i]))));
            }
        }
        buf ^= 1;
        float* hn = hs + buf * (RPC * LAT);
#pragma unroll
        for (int i = 0; i < RPC; i++) hn[i * LAT + j] = acc[i];
        if (pass == 1) {
#pragma unroll
            for (int i = 0; i < RPC; i++) {
                size_t pos = (size_t)(b0r + i) * SEQ + t;
                u16 h, lo;
                split2(acc[i], h, lo);
                g_z1h[pos * LAT + j] = h;
                g_z1l[pos * LAT + j] = lo;
            }
        }
        __syncthreads();
    }
    if (pass == 0) {
#pragma unroll
        for (int i = 0; i < RPC; i++)
            g_lend[(chunk * BATCH + (b0r + i)) * LAT + j] = hs[buf * (RPC * LAT) + i * LAT + j];
    }
}

// ---------------- boundary scan via A^32 ----------------
__global__ void __launch_bounds__(128) k_bound()
{
    extern __shared__ float smf[];
    float* As = smf;
    float* sv = smf + LAT * LAT;
    int j = threadIdx.x;
    int b = blockIdx.x;
    for (int idx = j; idx < LAT * LAT; idx += 128) As[idx] = g_Ap0[idx];
    float s = g_h0[b * LAT + j];
    for (int k = 0; k < NCHUNK; k++) {
        g_sk[(k * BATCH + b) * LAT + j] = s;
        sv[j] = s;
        __syncthreads();
        float acc = g_lend[(k * BATCH + b) * LAT + j];
#pragma unroll 8
        for (int m4 = 0; m4 < LAT; m4 += 4) {
            float a0 = As[(m4+0)*LAT + j], a1 = As[(m4+1)*LAT + j];
            float a2 = As[(m4+2)*LAT + j], a3 = As[(m4+3)*LAT + j];
            float4 h = *(const float4*)&sv[m4];
            acc = fmaf(h.x, a0, fmaf(h.y, a1, fmaf(h.z, a2, fmaf(h.w, a3, acc))));
        }
        __syncthreads();
        s = acc;
    }
}

// ---------------- launch ----------------
extern "C" void kernel_launch(void* const* d_in, const int* in_sizes, int n_in,
                              void* d_out, int out_size)
{
    const float* in  = (const float*)d_in[0];
    const float* ew0 = (const float*)d_in[1];
    const float* eb0 = (const float*)d_in[2];
    const float* ew1 = (const float*)d_in[3];
    const float* eb1 = (const float*)d_in[4];
    const float* ew2 = (const float*)d_in[5];
    const float* eb2 = (const float*)d_in[6];
    const float* gam = (const float*)d_in[7];
    const float* bet = (const float*)d_in[8];
    const float* Aw  = (const float*)d_in[9];
    const float* Bd  = (const float*)d_in[10];
    const float* dw0 = (const float*)d_in[11];
    const float* db0 = (const float*)d_in[12];
    const float* dw1 = (const float*)d_in[13];
    const float* db1 = (const float*)d_in[14];
    const float* dw2 = (const float*)d_in[15];
    const float* db2 = (const float*)d_in[16];
    float* out = (float*)d_out;

    u16 *a1h, *a1l, *a2h, *a2l, *z1h, *z1l;
    u16 *we0h, *we0l, *we1h, *we1l, *we2h, *we2l, *wd0h, *wd0l, *wd1h, *wd1l, *wd2h, *wd2l;
    cudaGetSymbolAddress((void**)&a1h, g_a1h); cudaGetSymbolAddress((void**)&a1l, g_a1l);
    cudaGetSymbolAddress((void**)&a2h, g_a2h); cudaGetSymbolAddress((void**)&a2l, g_a2l);
    cudaGetSymbolAddress((void**)&z1h, g_z1h); cudaGetSymbolAddress((void**)&z1l, g_z1l);
    cudaGetSymbolAddress((void**)&we0h, g_we0h); cudaGetSymbolAddress((void**)&we0l, g_we0l);
    cudaGetSymbolAddress((void**)&we1h, g_we1h); cudaGetSymbolAddress((void**)&we1l, g_we1l);
    cudaGetSymbolAddress((void**)&we2h, g_we2h); cudaGetSymbolAddress((void**)&we2l, g_we2l);
    cudaGetSymbolAddress((void**)&wd0h, g_wd0h); cudaGetSymbolAddress((void**)&wd0l, g_wd0l);
    cudaGetSymbolAddress((void**)&wd1h, g_wd1h); cudaGetSymbolAddress((void**)&wd1l, g_wd1l);
    cudaGetSymbolAddress((void**)&wd2h, g_wd2h); cudaGetSymbolAddress((void**)&wd2l, g_wd2l);

    // smem: ST=1 (enc L0): 4*18432+1536 = 75264
    //       ST=2 NT=128: 8*18432+1536  = 148992
    //       ST=2 NT=64:  4*18432+4*9216+1536 = 112128
    const int SM_L0   = 75264;
    const int SM_P128 = 148992;
    const int SM_P64  = 112128;

    cudaFuncSetAttribute(k_sq,    cudaFuncAttributeMaxDynamicSharedMemorySize, 65536);
    cudaFuncSetAttribute(k_pass,  cudaFuncAttributeMaxDynamicSharedMemorySize, 73728);
    cudaFuncSetAttribute(k_bound, cudaFuncAttributeMaxDynamicSharedMemorySize, 66560);
    cudaFuncSetAttribute(k_gemm<64,128,0,0>,  cudaFuncAttributeMaxDynamicSharedMemorySize, SM_L0);
    cudaFuncSetAttribute(k_gemm<256,128,0,1>, cudaFuncAttributeMaxDynamicSharedMemorySize, SM_P128);
    cudaFuncSetAttribute(k_gemm<256,128,1,1>, cudaFuncAttributeMaxDynamicSharedMemorySize, SM_P128);
    cudaFuncSetAttribute(k_gemm<128,128,0,1>, cudaFuncAttributeMaxDynamicSharedMemorySize, SM_P128);
    cudaFuncSetAttribute(k_gemm<256,64,2,1>,  cudaFuncAttributeMaxDynamicSharedMemorySize, SM_P64);

    static cudaStream_t sB = nullptr;
    static cudaEvent_t evF = nullptr, evB = nullptr;
    if (!sB) {
        cudaStreamCreateWithFlags(&sB, cudaStreamNonBlocking);
        cudaEventCreateWithFlags(&evF, cudaEventDisableTiming);
        cudaEventCreateWithFlags(&evB, cudaEventDisableTiming);
    }

    cudaEventRecord(evF, 0);

    // ---- stream 0: encoder ----
    k_init<<<1, 128>>>();
    k_prepw<<<(64*256+255)/256,  256>>>(ew0, 64, 256, 128, we0h, we0l);
    k_prepw<<<(256*256+255)/256, 256>>>(ew1, 256, 256, 128, we1h, we1l);
    k_prepw<<<(256*128+255)/256, 256>>>(ew2, 256, 128, 128, we2h, we2l);
    k_gemm<64,128,0,0><<<dim3(512,2), 256, SM_L0>>>(in, nullptr, nullptr, IND,
        we0h, we0l, eb0, a1h, a1l, nullptr, 256);
    k_gemm<256,128,0,1><<<dim3(512,2), 256, SM_P128>>>(nullptr, a1h, a1l, 256,
        we1h, we1l, eb1, a2h, a2l, nullptr, 256);
    k_gemm<256,128,1,1><<<dim3(512,1), 256, SM_P128>>>(nullptr, a2h, a2l, 256,
        we2h, we2l, eb2, nullptr, nullptr, nullptr, 0);
    k_fin<<<1, 128>>>(gam, bet);

    // ---- stream B: pass0 first (no deps), then A^32 chain, then dec preps ----
    cudaStreamWaitEvent(sB, evF, 0);
    k_pass<<<dim3(NCHUNK, NBS), 128, 73728, sB>>>(in, Aw, Bd, 0);
    for (int s = 0; s < 5; s++) k_sq<<<32, 512, 65536, sB>>>(Aw, s);
    k_prepw<<<(128*256+255)/256, 256, 0, sB>>>(dw0, 128, 256, 128, wd0h, wd0l);
    k_prepw<<<(256*256+255)/256, 256, 0, sB>>>(dw1, 256, 256, 128, wd1h, wd1l);
    k_prepw<<<(256*64+255)/256,  256, 0, sB>>>(dw2, 256, 64, 64, wd2h, wd2l);
    cudaEventRecord(evB, sB);

    // ---- join, serial tail ----
    cudaStreamWaitEvent(0, evB, 0);
    k_bound<<<BATCH, 128, 66560>>>();
    k_pass<<<dim3(NCHUNK, NBS), 128, 73728>>>(in, Aw, Bd, 1);
    k_gemm<128,128,0,1><<<dim3(512,2), 256, SM_P128>>>(nullptr, z1h, z1l, 128,
        wd0h, wd0l, db0, a1h, a1l, nullptr, 256);
    k_gemm<256,128,0,1><<<dim3(512,2), 256, SM_P128>>>(nullptr, a1h, a1l, 256,
        wd1h, wd1l, db1, a2h, a2l, nullptr, 256);
    k_gemm<256,64,2,1><<<dim3(512,1), 256, SM_P64>>>(nullptr, a2h, a2l, 256,
        wd2h, wd2l, db2, nullptr, nullptr, out, 64);
}

// round 10
// speedup vs baseline: 1.1230x; 1.1230x over previous
#include <cuda_runtime.h>
#include <cuda_bf16.h>
#include <cstdint>

typedef unsigned short u16;
typedef unsigned int u32;

#define BATCH 32
#define SEQ   2048
#define STATE 64
#define LAT   128
#define ENC   256
#define IND   320
#define NPOS  (BATCH*SEQ)
#define NCHUNK 64
#define CLEN   32
#define RPC    8
#define NBS    4

// ---------------- device scratch ----------------
__device__ float g_sum[LAT];
__device__ float g_sumsq[LAT];
__device__ float g_z0[BATCH*LAT];
__device__ float g_h0[BATCH*LAT];
__device__ float g_Ap0[LAT*LAT];
__device__ float g_Ap1[LAT*LAT];
__device__ float g_lend[NCHUNK*BATCH*LAT];
__device__ float g_sk[NCHUNK*BATCH*LAT];
__device__ u16 g_a1h[(size_t)NPOS*ENC], g_a1l[(size_t)NPOS*ENC];
__device__ u16 g_a2h[(size_t)NPOS*ENC], g_a2l[(size_t)NPOS*ENC];
__device__ u16 g_z1h[(size_t)NPOS*LAT], g_z1l[(size_t)NPOS*LAT];
__device__ __align__(16) u16 g_we0h[256*1*72], g_we0l[256*1*72];
__device__ __align__(16) u16 g_we1h[256*4*72], g_we1l[256*4*72];
__device__ __align__(16) u16 g_we2h[128*4*72], g_we2l[128*4*72];
__device__ __align__(16) u16 g_wd0h[256*2*72], g_wd0l[256*2*72];
__device__ __align__(16) u16 g_wd1h[256*4*72], g_wd1l[256*4*72];
__device__ __align__(16) u16 g_wd2h[64*4*72],  g_wd2l[64*4*72];

// ---------------- helpers ----------------
__device__ __forceinline__ u32 smem_u32(const void* p) {
    u32 a;
    asm("{ .reg .u64 t; cvta.to.shared.u64 t, %1; cvt.u32.u64 %0, t; }" : "=r"(a) : "l"(p));
    return a;
}
#define LDSM4(r, a) \
    asm volatile("ldmatrix.sync.aligned.m8n8.x4.shared.b16 {%0,%1,%2,%3}, [%4];" \
        : "=r"((r)[0]), "=r"((r)[1]), "=r"((r)[2]), "=r"((r)[3]) : "r"(a))
#define MMA(d, a, b) \
    asm volatile("mma.sync.aligned.m16n8k16.row.col.f32.bf16.bf16.f32 " \
        "{%0,%1,%2,%3},{%4,%5,%6,%7},{%8,%9},{%0,%1,%2,%3};" \
        : "+f"((d)[0]), "+f"((d)[1]), "+f"((d)[2]), "+f"((d)[3]) \
        : "r"((a)[0]), "r"((a)[1]), "r"((a)[2]), "r"((a)[3]), "r"((b)[0]), "r"((b)[1]))
#define CPA16(dst, src) asm volatile("cp.async.cg.shared.global [%0], [%1], 16;" :: "r"(dst), "l"(src))
#define CPA_COMMIT()  asm volatile("cp.async.commit_group;" ::: "memory")
#define CPA_WAIT0()   asm volatile("cp.async.wait_group 0;" ::: "memory")
#define CPA_WAIT1()   asm volatile("cp.async.wait_group 1;" ::: "memory")

__device__ __forceinline__ u16 bfh(float v) {
    __nv_bfloat16 b = __float2bfloat16(v);
    return *(u16*)&b;
}
__device__ __forceinline__ void split2(float v, u16& h, u16& l) {
    __nv_bfloat16 b = __float2bfloat16(v);
    h = *(u16*)&b;
    l = bfh(v - __bfloat162float(b));
}

// ---------------- small kernels ----------------
__global__ void k_init() {
    int t = threadIdx.x;
    if (t < LAT) { g_sum[t] = 0.f; g_sumsq[t] = 0.f; }
}

__global__ void k_sq(const float* __restrict__ Aw, int step) {
    extern __shared__ float S[];
    const float* src = (step == 0) ? Aw : ((step & 1) ? g_Ap0 : g_Ap1);
    float* dst = (step & 1) ? g_Ap1 : g_Ap0;
    int t = threadIdx.x;
    for (int i = t; i < LAT*LAT; i += 512) S[i] = src[i];
    __syncthreads();
    int base = blockIdx.x * 512 + t;
    int i = base >> 7, j = base & 127;
    float acc = 0.f;
#pragma unroll 8
    for (int k = 0; k < LAT; k++) acc = fmaf(S[i*LAT + k], S[k*LAT + j], acc);
    dst[base] = acc;
}

__global__ void k_prepw(const float* __restrict__ W, int K, int N, int NT,
                        u16* __restrict__ oh, u16* __restrict__ ol) {
    int idx = blockIdx.x * 256 + threadIdx.x;
    if (idx >= K * N) return;
    int k = idx / N, n = idx % N;
    int NCH = K >> 6;
    int nt = n / NT, nloc = n % NT, c = k >> 6, kl = k & 63;
    u16 h, l;
    split2(W[idx], h, l);
    size_t d = ((size_t)(nt * NCH + c) * NT + nloc) * 72 + kl;
    oh[d] = h; ol[d] = l;
}

// ---------------- HMMA GEMM: A single-buffered, W double-buffered ----------------
template<int K, int NT, int EPI, int ASRC>
__global__ void __launch_bounds__(256, 2) k_gemm(
    const float* __restrict__ A32, const u16* __restrict__ Ah, const u16* __restrict__ Al, int lda,
    const u16* __restrict__ Wh, const u16* __restrict__ Wl,
    const float* __restrict__ bias,
    u16* __restrict__ Oh, u16* __restrict__ Ol, float* __restrict__ outF, int ldo)
{
    constexpr int KC  = 64;
    constexpr int NCH = K / KC;
    constexpr int WST = (NCH > 1) ? 2 : 1;   // W stages
    constexpr int SMA = 128 * 144;
    constexpr int SMW = NT * 144;
    constexpr int SB  = 2*SMA + 2*WST*SMW;
    constexpr int MT  = (NT == 128) ? 2 : 1;
    constexpr int WM  = (NT == 128) ? 4 : 8;

    extern __shared__ char sm[];
    u32 sb = smem_u32(sm);
    int tid = threadIdx.x, wid = tid >> 5, l = tid & 31;
    int wm = wid % WM, wn = wid / WM;
    int tile = blockIdx.x, nt = blockIdx.y, nt0 = nt * NT;
    int RW = wm * (MT * 16);

    float* sbias = (float*)(sm + SB);
    float* ssum  = (float*)(sm + SB + 512);
    float* ssq   = (float*)(sm + SB + 1024);
    if (tid < NT) sbias[tid] = bias[nt0 + tid];
    if (EPI == 1 && tid < 128) { ssum[tid] = 0.f; ssq[tid] = 0.f; }

    float acc[MT][8][4];
#pragma unroll
    for (int mt = 0; mt < MT; mt++)
#pragma unroll
        for (int n = 0; n < 8; n++)
#pragma unroll
            for (int i = 0; i < 4; i++) acc[mt][n][i] = 0.f;

    u32 aoff = (RW + (l & 15)) * 144 + (l >> 4) * 16;
    u32 boff = (wn*64 + (l & 7) + ((l >> 4) * 8)) * 144 + (((l >> 3) & 1) * 16);

    u32 sAh = sb, sAl = sb + SMA;
    auto baseWh = [&](int s){ return sb + 2*SMA + s*SMW; };
    auto baseWl = [&](int s){ return sb + 2*SMA + WST*SMW + s*SMW; };

    auto loadW = [&](int c, int s) {
        const u16* wh = Wh + (size_t)(nt * NCH + c) * NT * 72;
        const u16* wl = Wl + (size_t)(nt * NCH + c) * NT * 72;
        u32 bWh = baseWh(s), bWl = baseWl(s);
#pragma unroll
        for (int i = tid; i < NT * 9; i += 256) {
            CPA16(bWh + i*16, wh + i*8);
            CPA16(bWl + i*16, wl + i*8);
        }
    };
    auto loadA = [&](int c) {
#pragma unroll
        for (int i = tid; i < 1024; i += 256) {
            int row = i >> 3, seg = i & 7;
            size_t go = (size_t)(tile*128 + row) * lda + c*KC + seg*8;
            u32 d = row*144 + seg*16;
            CPA16(sAh + d, Ah + go);
            CPA16(sAl + d, Al + go);
        }
    };

    // prologue: chunk 0
    loadW(0, 0);
    if (ASRC == 1) {
        loadA(0);
    } else {   // enc L0: register split of fp32 A (single chunk)
        int r = tid & 127, kh = (tid >> 7) * 32;
        const float* ap = A32 + (size_t)(tile*128 + r) * lda + kh;
#pragma unroll
        for (int j = 0; j < 4; j++) {
            float4 f0 = *(const float4*)(ap + j*8);
            float4 f1 = *(const float4*)(ap + j*8 + 4);
            float f[8] = {f0.x,f0.y,f0.z,f0.w,f1.x,f1.y,f1.z,f1.w};
            union { u16 us[8]; uint4 u; } ph, pl;
#pragma unroll
            for (int q = 0; q < 8; q++) split2(f[q], ph.us[q], pl.us[q]);
            int off = r*144 + (kh + j*8)*2;
            *(uint4*)(sm + off)       = ph.u;
            *(uint4*)(sm + SMA + off) = pl.u;
        }
    }
    CPA_COMMIT();

    for (int c = 0; c < NCH; c++) {
        int sW = c & (WST - 1);
        bool pre = (WST == 2) && (c + 1 < NCH);
        if (pre) { loadW(c + 1, (c + 1) & 1); CPA_COMMIT(); }
        if (pre) CPA_WAIT1(); else CPA_WAIT0();
        __syncthreads();

        u32 sWh = baseWh(sW), sWl = baseWl(sW);
#pragma unroll
        for (int ks = 0; ks < 4; ks++) {
            int k2 = ks * 32;
            u32 ah[MT][4], al[MT][4], bf[4][4];
#pragma unroll
            for (int mt = 0; mt < MT; mt++) LDSM4(ah[mt], sAh + aoff + mt*2304 + k2);
#pragma unroll
            for (int mt = 0; mt < MT; mt++) LDSM4(al[mt], sAl + aoff + mt*2304 + k2);
#pragma unroll
            for (int p = 0; p < 4; p++)     LDSM4(bf[p], sWh + boff + p*2304 + k2);
#pragma unroll
            for (int mt = 0; mt < MT; mt++)
#pragma unroll
                for (int p = 0; p < 4; p++) {
                    MMA(acc[mt][2*p],   ah[mt], bf[p]);
                    MMA(acc[mt][2*p+1], ah[mt], &bf[p][2]);
                }
#pragma unroll
            for (int mt = 0; mt < MT; mt++)
#pragma unroll
                for (int p = 0; p < 4; p++) {
                    MMA(acc[mt][2*p],   al[mt], bf[p]);
                    MMA(acc[mt][2*p+1], al[mt], &bf[p][2]);
                }
#pragma unroll
            for (int p = 0; p < 4; p++)     LDSM4(bf[p], sWl + boff + p*2304 + k2);
#pragma unroll
            for (int mt = 0; mt < MT; mt++)
#pragma unroll
                for (int p = 0; p < 4; p++) {
                    MMA(acc[mt][2*p],   ah[mt], bf[p]);
                    MMA(acc[mt][2*p+1], ah[mt], &bf[p][2]);
                }
        }
        __syncthreads();
        if (ASRC == 1 && c + 1 < NCH) { loadA(c + 1); CPA_COMMIT(); }
    }

    int g = l >> 2, tg = l & 3;
#pragma unroll
    for (int mt = 0; mt < MT; mt++) {
        int row = tile*128 + RW + mt*16 + g;
#pragma unroll
        for (int n = 0; n < 8; n++) {
            int colL = wn*64 + n*8 + tg*2;
            float b0 = sbias[colL], b1 = sbias[colL + 1];
            float v0 = acc[mt][n][0] + b0, v1 = acc[mt][n][1] + b1;
            float v2 = acc[mt][n][2] + b0, v3 = acc[mt][n][3] + b1;
            if (EPI != 2) {
                v0 = fmaxf(v0, 0.f); v1 = fmaxf(v1, 0.f);
                v2 = fmaxf(v2, 0.f); v3 = fmaxf(v3, 0.f);
            }
            if (EPI == 1) {
                atomicAdd(&ssum[colL],     v0 + v2);
                atomicAdd(&ssq[colL],      v0*v0 + v2*v2);
                atomicAdd(&ssum[colL + 1], v1 + v3);
                atomicAdd(&ssq[colL + 1],  v1*v1 + v3*v3);
                if (((tile & 15) == 0) && g == 0 && wm == 0 && mt == 0) {
                    g_z0[(tile >> 4) * LAT + colL]     = v0;
                    g_z0[(tile >> 4) * LAT + colL + 1] = v1;
                }
            } else if (EPI == 0) {
                u16 h0,l0,h1,l1,h2,l2,h3,l3;
                split2(v0,h0,l0); split2(v1,h1,l1); split2(v2,h2,l2); split2(v3,h3,l3);
                size_t o0 = (size_t)row * ldo + nt0 + colL;
                size_t o1 = (size_t)(row + 8) * ldo + nt0 + colL;
                *(u32*)&Oh[o0] = (u32)h0 | ((u32)h1 << 16);
                *(u32*)&Ol[o0] = (u32)l0 | ((u32)l1 << 16);
                *(u32*)&Oh[o1] = (u32)h2 | ((u32)h3 << 16);
                *(u32*)&Ol[o1] = (u32)l2 | ((u32)l3 << 16);
            } else {
                *(float2*)&outF[(size_t)row * ldo + nt0 + colL]       = make_float2(v0, v1);
                *(float2*)&outF[(size_t)(row + 8) * ldo + nt0 + colL] = make_float2(v2, v3);
            }
        }
    }
    if (EPI == 1) {
        __syncthreads();
        if (tid < 128) {
            atomicAdd(&g_sum[tid],   ssum[tid]);
            atomicAdd(&g_sumsq[tid], ssq[tid]);
        }
    }
}

// ---------------- BN finalize ----------------
__global__ void k_fin(const float* __restrict__ gamma, const float* __restrict__ beta)
{
    int j = threadIdx.x;
    float inv = 1.f / (float)NPOS;
    float m  = g_sum[j] * inv;
    float v  = g_sumsq[j] * inv - m * m;
    float rs = rsqrtf(v + 1e-5f);
    float ga = gamma[j], be = beta[j];
    for (int b = 0; b < BATCH; b++) {
        float z = g_z0[b*LAT + j];
        g_h0[b*LAT + j] = (z - m) * rs * ga + be;
    }
}

// ---------------- chunked scan ----------------
__global__ void __launch_bounds__(128) k_pass(const float* __restrict__ in,
                                              const float* __restrict__ Aw,
                                              const float* __restrict__ Bd, int pass)
{
    extern __shared__ float smf[];
    float* As = smf;
    float* hs = smf + LAT * LAT;
    int j     = threadIdx.x;
    int chunk = blockIdx.x;
    int b0r   = blockIdx.y * RPC;

    for (int idx = j; idx < LAT * LAT; idx += 128) As[idx] = Aw[idx];
    float dj = fminf(fmaxf(Bd[j], -0.95f), 0.95f);
#pragma unroll
    for (int i = 0; i < RPC; i++) {
        float v = (pass == 0) ? 0.f : g_sk[(chunk * BATCH + (b0r + i)) * LAT + j];
        hs[i * LAT + j] = v;
    }
    __syncthreads();

    int t0 = chunk * CLEN;
    int buf = 0;
    for (int t = t0; t < t0 + CLEN; t++) {
        float acc[RPC];
#pragma unroll
        for (int i = 0; i < RPC; i++)
            acc[i] = in[((long)(b0r + i) * SEQ + t) * IND + (STATE + LAT) + j] * dj;

        const float* hb = hs + buf * (RPC * LAT);
#pragma unroll 8
        for (int k4 = 0; k4 < LAT; k4 += 4) {
            float a0 = As[(k4+0)*LAT + j], a1 = As[(k4+1)*LAT + j];
            float a2 = As[(k4+2)*LAT + j], a3 = As[(k4+3)*LAT + j];
#pragma unroll
            for (int i = 0; i < RPC; i++) {
                float4 h = *(const float4*)&hb[i * LAT + k4];
                acc[i] = fmaf(h.x, a0, fmaf(h.y, a1, fmaf(h.z, a2, fmaf(h.w, a3, acc[i]))));
            }
        }
        buf ^= 1;
        float* hn = hs + buf * (RPC * LAT);
#pragma unroll
        for (int i = 0; i < RPC; i++) hn[i * LAT + j] = acc[i];
        if (pass == 1) {
#pragma unroll
            for (int i = 0; i < RPC; i++) {
                size_t pos = (size_t)(b0r + i) * SEQ + t;
                u16 h, lo;
                split2(acc[i], h, lo);
                g_z1h[pos * LAT + j] = h;
                g_z1l[pos * LAT + j] = lo;
            }
        }
        __syncthreads();
    }
    if (pass == 0) {
#pragma unroll
        for (int i = 0; i < RPC; i++)
            g_lend[(chunk * BATCH + (b0r + i)) * LAT + j] = hs[buf * (RPC * LAT) + i * LAT + j];
    }
}

// ---------------- boundary scan via A^32 ----------------
__global__ void __launch_bounds__(128) k_bound()
{
    extern __shared__ float smf[];
    float* As = smf;
    float* sv = smf + LAT * LAT;
    int j = threadIdx.x;
    int b = blockIdx.x;
    for (int idx = j; idx < LAT * LAT; idx += 128) As[idx] = g_Ap0[idx];
    float s = g_h0[b * LAT + j];
    for (int k = 0; k < NCHUNK; k++) {
        g_sk[(k * BATCH + b) * LAT + j] = s;
        sv[j] = s;
        __syncthreads();
        float acc = g_lend[(k * BATCH + b) * LAT + j];
#pragma unroll 8
        for (int m4 = 0; m4 < LAT; m4 += 4) {
            float a0 = As[(m4+0)*LAT + j], a1 = As[(m4+1)*LAT + j];
            float a2 = As[(m4+2)*LAT + j], a3 = As[(m4+3)*LAT + j];
            float4 h = *(const float4*)&sv[m4];
            acc = fmaf(h.x, a0, fmaf(h.y, a1, fmaf(h.z, a2, fmaf(h.w, a3, acc))));
        }
        __syncthreads();
        s = acc;
    }
}

// ---------------- launch ----------------
extern "C" void kernel_launch(void* const* d_in, const int* in_sizes, int n_in,
                              void* d_out, int out_size)
{
    const float* in  = (const float*)d_in[0];
    const float* ew0 = (const float*)d_in[1];
    const float* eb0 = (const float*)d_in[2];
    const float* ew1 = (const float*)d_in[3];
    const float* eb1 = (const float*)d_in[4];
    const float* ew2 = (const float*)d_in[5];
    const float* eb2 = (const float*)d_in[6];
    const float* gam = (const float*)d_in[7];
    const float* bet = (const float*)d_in[8];
    const float* Aw  = (const float*)d_in[9];
    const float* Bd  = (const float*)d_in[10];
    const float* dw0 = (const float*)d_in[11];
    const float* db0 = (const float*)d_in[12];
    const float* dw1 = (const float*)d_in[13];
    const float* db1 = (const float*)d_in[14];
    const float* dw2 = (const float*)d_in[15];
    const float* db2 = (const float*)d_in[16];
    float* out = (float*)d_out;

    u16 *a1h, *a1l, *a2h, *a2l, *z1h, *z1l;
    u16 *we0h, *we0l, *we1h, *we1l, *we2h, *we2l, *wd0h, *wd0l, *wd1h, *wd1l, *wd2h, *wd2l;
    cudaGetSymbolAddress((void**)&a1h, g_a1h); cudaGetSymbolAddress((void**)&a1l, g_a1l);
    cudaGetSymbolAddress((void**)&a2h, g_a2h); cudaGetSymbolAddress((void**)&a2l, g_a2l);
    cudaGetSymbolAddress((void**)&z1h, g_z1h); cudaGetSymbolAddress((void**)&z1l, g_z1l);
    cudaGetSymbolAddress((void**)&we0h, g_we0h); cudaGetSymbolAddress((void**)&we0l, g_we0l);
    cudaGetSymbolAddress((void**)&we1h, g_we1h); cudaGetSymbolAddress((void**)&we1l, g_we1l);
    cudaGetSymbolAddress((void**)&we2h, g_we2h); cudaGetSymbolAddress((void**)&we2l, g_we2l);
    cudaGetSymbolAddress((void**)&wd0h, g_wd0h); cudaGetSymbolAddress((void**)&wd0l, g_wd0l);
    cudaGetSymbolAddress((void**)&wd1h, g_wd1h); cudaGetSymbolAddress((void**)&wd1l, g_wd1l);
    cudaGetSymbolAddress((void**)&wd2h, g_wd2h); cudaGetSymbolAddress((void**)&wd2l, g_wd2l);

    // smem: L0 (WST=1,NT=128): 2*18432 + 2*18432 + 1536 = 75264
    //       WST=2 NT=128: 2*18432 + 4*18432 + 1536 = 112128  (2 CTAs/SM: 224256 <= 233472)
    //       WST=2 NT=64:  2*18432 + 4*9216  + 1536 = 75264
    const int SM_L0   = 75264;
    const int SM_P128 = 112128;
    const int SM_P64  = 75264;

    cudaFuncSetAttribute(k_sq,    cudaFuncAttributeMaxDynamicSharedMemorySize, 65536);
    cudaFuncSetAttribute(k_pass,  cudaFuncAttributeMaxDynamicSharedMemorySize, 73728);
    cudaFuncSetAttribute(k_bound, cudaFuncAttributeMaxDynamicSharedMemorySize, 66560);
    cudaFuncSetAttribute(k_gemm<64,128,0,0>,  cudaFuncAttributeMaxDynamicSharedMemorySize, SM_L0);
    cudaFuncSetAttribute(k_gemm<256,128,0,1>, cudaFuncAttributeMaxDynamicSharedMemorySize, SM_P128);
    cudaFuncSetAttribute(k_gemm<256,128,1,1>, cudaFuncAttributeMaxDynamicSharedMemorySize, SM_P128);
    cudaFuncSetAttribute(k_gemm<128,128,0,1>, cudaFuncAttributeMaxDynamicSharedMemorySize, SM_P128);
    cudaFuncSetAttribute(k_gemm<256,64,2,1>,  cudaFuncAttributeMaxDynamicSharedMemorySize, SM_P64);

    static cudaStream_t sB = nullptr;
    static cudaEvent_t evF = nullptr, evB = nullptr;
    if (!sB) {
        cudaStreamCreateWithFlags(&sB, cudaStreamNonBlocking);
        cudaEventCreateWithFlags(&evF, cudaEventDisableTiming);
        cudaEventCreateWithFlags(&evB, cudaEventDisableTiming);
    }

    cudaEventRecord(evF, 0);

    // ---- stream 0: encoder ----
    k_init<<<1, 128>>>();
    k_prepw<<<(64*256+255)/256,  256>>>(ew0, 64, 256, 128, we0h, we0l);
    k_prepw<<<(256*256+255)/256, 256>>>(ew1, 256, 256, 128, we1h, we1l);
    k_prepw<<<(256*128+255)/256, 256>>>(ew2, 256, 128, 128, we2h, we2l);
    k_gemm<64,128,0,0><<<dim3(512,2), 256, SM_L0>>>(in, nullptr, nullptr, IND,
        we0h, we0l, eb0, a1h, a1l, nullptr, 256);
    k_gemm<256,128,0,1><<<dim3(512,2), 256, SM_P128>>>(nullptr, a1h, a1l, 256,
        we1h, we1l, eb1, a2h, a2l, nullptr, 256);
    k_gemm<256,128,1,1><<<dim3(512,1), 256, SM_P128>>>(nullptr, a2h, a2l, 256,
        we2h, we2l, eb2, nullptr, nullptr, nullptr, 0);
    k_fin<<<1, 128>>>(gam, bet);

    // ---- stream B: pass0 first (no deps), then A^32 chain, then dec preps ----
    cudaStreamWaitEvent(sB, evF, 0);
    k_pass<<<dim3(NCHUNK, NBS), 128, 73728, sB>>>(in, Aw, Bd, 0);
    for (int s = 0; s < 5; s++) k_sq<<<32, 512, 65536, sB>>>(Aw, s);
    k_prepw<<<(128*256+255)/256, 256, 0, sB>>>(dw0, 128, 256, 128, wd0h, wd0l);
    k_prepw<<<(256*256+255)/256, 256, 0, sB>>>(dw1, 256, 256, 128, wd1h, wd1l);
    k_prepw<<<(256*64+255)/256,  256, 0, sB>>>(dw2, 256, 64, 64, wd2h, wd2l);
    cudaEventRecord(evB, sB);

    // ---- join, serial tail ----
    cudaStreamWaitEvent(0, evB, 0);
    k_bound<<<BATCH, 128, 66560>>>();
    k_pass<<<dim3(NCHUNK, NBS), 128, 73728>>>(in, Aw, Bd, 1);
    k_gemm<128,128,0,1><<<dim3(512,2), 256, SM_P128>>>(nullptr, z1h, z1l, 128,
        wd0h, wd0l, db0, a1h, a1l, nullptr, 256);
    k_gemm<256,128,0,1><<<dim3(512,2), 256, SM_P128>>>(nullptr, a1h, a1l, 256,
        wd1h, wd1l, db1, a2h, a2l, nullptr, 256);
    k_gemm<256,64,2,1><<<dim3(512,1), 256, SM_P64>>>(nullptr, a2h, a2l, 256,
        wd2h, wd2l, db2, nullptr, nullptr, out, 64);
}

// round 11
// speedup vs baseline: 1.4139x; 1.2590x over previous
#include <cuda_runtime.h>
#include <cuda_fp16.h>
#include <cstdint>

typedef unsigned short u16;
typedef unsigned int u32;

#define BATCH 32
#define SEQ   2048
#define STATE 64
#define LAT   128
#define ENC   256
#define IND   320
#define NPOS  (BATCH*SEQ)
#define NCHUNK 64
#define CLEN   32
#define RPC    8
#define NBS    4

// ---------------- device scratch ----------------
__device__ float g_sum[LAT];
__device__ float g_sumsq[LAT];
__device__ float g_z0[BATCH*LAT];
__device__ float g_h0[BATCH*LAT];
__device__ float g_Ap0[LAT*LAT];
__device__ float g_Ap1[LAT*LAT];
__device__ float g_lend[NCHUNK*BATCH*LAT];
__device__ float g_sk[NCHUNK*BATCH*LAT];
// fp16 activations (single array each)
__device__ u16 g_a1[(size_t)NPOS*ENC];
__device__ u16 g_a2[(size_t)NPOS*ENC];
__device__ u16 g_z1[(size_t)NPOS*LAT];
// packed fp16 weight images (chunk-blocked, 72-half padded rows, transposed [n][k]); hi+lo
__device__ __align__(16) u16 g_we0h[256*1*72], g_we0l[256*1*72];
__device__ __align__(16) u16 g_we1h[256*4*72], g_we1l[256*4*72];
__device__ __align__(16) u16 g_we2h[128*4*72], g_we2l[128*4*72];
__device__ __align__(16) u16 g_wd0h[256*2*72], g_wd0l[256*2*72];
__device__ __align__(16) u16 g_wd1h[256*4*72], g_wd1l[256*4*72];
__device__ __align__(16) u16 g_wd2h[64*4*72],  g_wd2l[64*4*72];

// ---------------- helpers ----------------
__device__ __forceinline__ u32 smem_u32(const void* p) {
    u32 a;
    asm("{ .reg .u64 t; cvta.to.shared.u64 t, %1; cvt.u32.u64 %0, t; }" : "=r"(a) : "l"(p));
    return a;
}
#define LDSM4(r, a) \
    asm volatile("ldmatrix.sync.aligned.m8n8.x4.shared.b16 {%0,%1,%2,%3}, [%4];" \
        : "=r"((r)[0]), "=r"((r)[1]), "=r"((r)[2]), "=r"((r)[3]) : "r"(a))
#define MMA(d, a, b) \
    asm volatile("mma.sync.aligned.m16n8k16.row.col.f32.f16.f16.f32 " \
        "{%0,%1,%2,%3},{%4,%5,%6,%7},{%8,%9},{%0,%1,%2,%3};" \
        : "+f"((d)[0]), "+f"((d)[1]), "+f"((d)[2]), "+f"((d)[3]) \
        : "r"((a)[0]), "r"((a)[1]), "r"((a)[2]), "r"((a)[3]), "r"((b)[0]), "r"((b)[1]))
#define CPA16(dst, src) asm volatile("cp.async.cg.shared.global [%0], [%1], 16;" :: "r"(dst), "l"(src))
#define CPA_FLUSH() asm volatile("cp.async.commit_group;\ncp.async.wait_group 0;" ::: "memory")

__device__ __forceinline__ u16 h_bits(__half h) { return *(u16*)&h; }
__device__ __forceinline__ u16 f2h(float v) { __half h = __float2half(v); return h_bits(h); }
__device__ __forceinline__ void split2h(float v, u16& h, u16& l) {
    __half b = __float2half(v);
    h = h_bits(b);
    l = f2h(v - __half2float(b));
}

// ---------------- small kernels ----------------
__global__ void k_init() {
    int t = threadIdx.x;
    if (t < LAT) { g_sum[t] = 0.f; g_sumsq[t] = 0.f; }
}

__global__ void k_sq(const float* __restrict__ Aw, int step) {
    extern __shared__ float S[];
    const float* src = (step == 0) ? Aw : ((step & 1) ? g_Ap0 : g_Ap1);
    float* dst = (step & 1) ? g_Ap1 : g_Ap0;
    int t = threadIdx.x;
    for (int i = t; i < LAT*LAT; i += 512) S[i] = src[i];
    __syncthreads();
    int base = blockIdx.x * 512 + t;
    int i = base >> 7, j = base & 127;
    float acc = 0.f;
#pragma unroll 8
    for (int k = 0; k < LAT; k++) acc = fmaf(S[i*LAT + k], S[k*LAT + j], acc);
    dst[base] = acc;
}

__global__ void k_prepw(const float* __restrict__ W, int K, int N, int NT,
                        u16* __restrict__ oh, u16* __restrict__ ol) {
    int idx = blockIdx.x * 256 + threadIdx.x;
    if (idx >= K * N) return;
    int k = idx / N, n = idx % N;
    int NCH = K >> 6;
    int nt = n / NT, nloc = n % NT, c = k >> 6, kl = k & 63;
    u16 h, l;
    split2h(W[idx], h, l);
    size_t d = ((size_t)(nt * NCH + c) * NT + nloc) * 72 + kl;
    oh[d] = h; ol[d] = l;
}

// ---------------- HMMA GEMM: fp16, A hi-only (1 array), W hi+lo (2 passes) ----------------
// EPI 0: bias+relu -> fp16 out; EPI 1: BN stats + z0; EPI 2: bias -> fp32 out
// ASRC 0: A fp32 (hi-split on load); 1: A fp16 array
template<int K, int NT, int EPI, int ASRC>
__global__ void __launch_bounds__(256, 2) k_gemm(
    const float* __restrict__ A32, const u16* __restrict__ Ax, int lda,
    const u16* __restrict__ Wh, const u16* __restrict__ Wl,
    const float* __restrict__ bias,
    u16* __restrict__ Ox, float* __restrict__ outF, int ldo)
{
    constexpr int KC  = 64;
    constexpr int NCH = K / KC;
    constexpr int SMA = 128 * 144;       // one A array (fp16 hi)
    constexpr int SMW = NT * 144;
    constexpr int SB  = SMA + 2*SMW;
    constexpr int MT  = (NT == 128) ? 2 : 1;
    constexpr int WM  = (NT == 128) ? 4 : 8;

    extern __shared__ char sm[];
    u32 sb = smem_u32(sm);
    int tid = threadIdx.x, wid = tid >> 5, l = tid & 31;
    int wm = wid % WM, wn = wid / WM;
    int tile = blockIdx.x, nt = blockIdx.y, nt0 = nt * NT;
    int RW = wm * (MT * 16);

    float* sbias = (float*)(sm + SB);
    float* ssum  = (float*)(sm + SB + 512);
    float* ssq   = (float*)(sm + SB + 1024);
    if (tid < NT) sbias[tid] = bias[nt0 + tid];
    if (EPI == 1 && tid < 128) { ssum[tid] = 0.f; ssq[tid] = 0.f; }

    float acc[MT][8][4];
#pragma unroll
    for (int mt = 0; mt < MT; mt++)
#pragma unroll
        for (int n = 0; n < 8; n++)
#pragma unroll
            for (int i = 0; i < 4; i++) acc[mt][n][i] = 0.f;

    u32 aoff = (RW + (l & 15)) * 144 + (l >> 4) * 16;
    u32 boff = (wn*64 + (l & 7) + ((l >> 4) * 8)) * 144 + (((l >> 3) & 1) * 16);
    u32 sA = sb, sWh = sb + SMA, sWl = sb + SMA + SMW;

    for (int c = 0; c < NCH; c++) {
        __syncthreads();
        // W chunk: both hi and lo images
        {
            const u16* wh = Wh + (size_t)(nt * NCH + c) * NT * 72;
            const u16* wl = Wl + (size_t)(nt * NCH + c) * NT * 72;
#pragma unroll
            for (int i = tid; i < NT * 9; i += 256) {
                CPA16(sWh + i*16, wh + i*8);
                CPA16(sWl + i*16, wl + i*8);
            }
        }
        // A chunk: single fp16 array
        if (ASRC == 1) {
#pragma unroll
            for (int i = tid; i < 1024; i += 256) {
                int row = i >> 3, seg = i & 7;
                size_t go = (size_t)(tile*128 + row) * lda + c*KC + seg*8;
                CPA16(sA + row*144 + seg*16, Ax + go);
            }
        } else {
            int r = tid & 127, kh = (tid >> 7) * 32;
            const float* ap = A32 + (size_t)(tile*128 + r) * lda + c*KC + kh;
#pragma unroll
            for (int j = 0; j < 4; j++) {
                float4 f0 = *(const float4*)(ap + j*8);
                float4 f1 = *(const float4*)(ap + j*8 + 4);
                float f[8] = {f0.x,f0.y,f0.z,f0.w,f1.x,f1.y,f1.z,f1.w};
                union { u16 us[8]; uint4 u; } ph;
#pragma unroll
                for (int q = 0; q < 8; q++) ph.us[q] = f2h(f[q]);
                *(uint4*)(sm + r*144 + (kh + j*8)*2) = ph.u;
            }
        }
        CPA_FLUSH();
        __syncthreads();
#pragma unroll
        for (int ks = 0; ks < 4; ks++) {
            int k2 = ks * 32;
            u32 af[MT][4], bf[4][4];
#pragma unroll
            for (int mt = 0; mt < MT; mt++) LDSM4(af[mt], sA + aoff + mt*2304 + k2);
#pragma unroll
            for (int p = 0; p < 4; p++)     LDSM4(bf[p], sWh + boff + p*2304 + k2);
#pragma unroll
            for (int mt = 0; mt < MT; mt++)
#pragma unroll
                for (int p = 0; p < 4; p++) {
                    MMA(acc[mt][2*p],   af[mt], bf[p]);
                    MMA(acc[mt][2*p+1], af[mt], &bf[p][2]);
                }
#pragma unroll
            for (int p = 0; p < 4; p++)     LDSM4(bf[p], sWl + boff + p*2304 + k2);
#pragma unroll
            for (int mt = 0; mt < MT; mt++)
#pragma unroll
                for (int p = 0; p < 4; p++) {
                    MMA(acc[mt][2*p],   af[mt], bf[p]);
                    MMA(acc[mt][2*p+1], af[mt], &bf[p][2]);
                }
        }
    }

    int g = l >> 2, tg = l & 3;
#pragma unroll
    for (int mt = 0; mt < MT; mt++) {
        int row = tile*128 + RW + mt*16 + g;
#pragma unroll
        for (int n = 0; n < 8; n++) {
            int colL = wn*64 + n*8 + tg*2;
            float b0 = sbias[colL], b1 = sbias[colL + 1];
            float v0 = acc[mt][n][0] + b0, v1 = acc[mt][n][1] + b1;
            float v2 = acc[mt][n][2] + b0, v3 = acc[mt][n][3] + b1;
            if (EPI != 2) {
                v0 = fmaxf(v0, 0.f); v1 = fmaxf(v1, 0.f);
                v2 = fmaxf(v2, 0.f); v3 = fmaxf(v3, 0.f);
            }
            if (EPI == 1) {
                atomicAdd(&ssum[colL],     v0 + v2);
                atomicAdd(&ssq[colL],      v0*v0 + v2*v2);
                atomicAdd(&ssum[colL + 1], v1 + v3);
                atomicAdd(&ssq[colL + 1],  v1*v1 + v3*v3);
                if (((tile & 15) == 0) && g == 0 && wm == 0 && mt == 0) {
                    g_z0[(tile >> 4) * LAT + colL]     = v0;
                    g_z0[(tile >> 4) * LAT + colL + 1] = v1;
                }
            } else if (EPI == 0) {
                size_t o0 = (size_t)row * ldo + nt0 + colL;
                size_t o1 = (size_t)(row + 8) * ldo + nt0 + colL;
                *(u32*)&Ox[o0] = (u32)f2h(v0) | ((u32)f2h(v1) << 16);
                *(u32*)&Ox[o1] = (u32)f2h(v2) | ((u32)f2h(v3) << 16);
            } else {
                *(float2*)&outF[(size_t)row * ldo + nt0 + colL]       = make_float2(v0, v1);
                *(float2*)&outF[(size_t)(row + 8) * ldo + nt0 + colL] = make_float2(v2, v3);
            }
        }
    }
    if (EPI == 1) {
        __syncthreads();
        if (tid < 128) {
            atomicAdd(&g_sum[tid],   ssum[tid]);
            atomicAdd(&g_sumsq[tid], ssq[tid]);
        }
    }
}

// ---------------- BN finalize ----------------
__global__ void k_fin(const float* __restrict__ gamma, const float* __restrict__ beta)
{
    int j = threadIdx.x;
    float inv = 1.f / (float)NPOS;
    float m  = g_sum[j] * inv;
    float v  = g_sumsq[j] * inv - m * m;
    float rs = rsqrtf(v + 1e-5f);
    float ga = gamma[j], be = beta[j];
    for (int b = 0; b < BATCH; b++) {
        float z = g_z0[b*LAT + j];
        g_h0[b*LAT + j] = (z - m) * rs * ga + be;
    }
}

// ---------------- chunked scan ----------------
__global__ void __launch_bounds__(128) k_pass(const float* __restrict__ in,
                                              const float* __restrict__ Aw,
                                              const float* __restrict__ Bd, int pass)
{
    extern __shared__ float smf[];
    float* As = smf;
    float* hs = smf + LAT * LAT;
    int j     = threadIdx.x;
    int chunk = blockIdx.x;
    int b0r   = blockIdx.y * RPC;

    for (int idx = j; idx < LAT * LAT; idx += 128) As[idx] = Aw[idx];
    float dj = fminf(fmaxf(Bd[j], -0.95f), 0.95f);
#pragma unroll
    for (int i = 0; i < RPC; i++) {
        float v = (pass == 0) ? 0.f : g_sk[(chunk * BATCH + (b0r + i)) * LAT + j];
        hs[i * LAT + j] = v;
    }
    __syncthreads();

    int t0 = chunk * CLEN;
    int buf = 0;
    for (int t = t0; t < t0 + CLEN; t++) {
        float acc[RPC];
#pragma unroll
        for (int i = 0; i < RPC; i++)
            acc[i] = in[((long)(b0r + i) * SEQ + t) * IND + (STATE + LAT) + j] * dj;

        const float* hb = hs + buf * (RPC * LAT);
#pragma unroll 8
        for (int k4 = 0; k4 < LAT; k4 += 4) {
            float a0 = As[(k4+0)*LAT + j], a1 = As[(k4+1)*LAT + j];
            float a2 = As[(k4+2)*LAT + j], a3 = As[(k4+3)*LAT + j];
#pragma unroll
            for (int i = 0; i < RPC; i++) {
                float4 h = *(const float4*)&hb[i * LAT + k4];
                acc[i] = fmaf(h.x, a0, fmaf(h.y, a1, fmaf(h.z, a2, fmaf(h.w, a3, acc[i]))));
            }
        }
        buf ^= 1;
        float* hn = hs + buf * (RPC * LAT);
#pragma unroll
        for (int i = 0; i < RPC; i++) hn[i * LAT + j] = acc[i];
        if (pass == 1) {
#pragma unroll
            for (int i = 0; i < RPC; i++) {
                size_t pos = (size_t)(b0r + i) * SEQ + t;
                g_z1[pos * LAT + j] = f2h(acc[i]);
            }
        }
        __syncthreads();
    }
    if (pass == 0) {
#pragma unroll
        for (int i = 0; i < RPC; i++)
            g_lend[(chunk * BATCH + (b0r + i)) * LAT + j] = hs[buf * (RPC * LAT) + i * LAT + j];
    }
}

// ---------------- boundary scan via A^32 ----------------
__global__ void __launch_bounds__(128) k_bound()
{
    extern __shared__ float smf[];
    float* As = smf;
    float* sv = smf + LAT * LAT;
    int j = threadIdx.x;
    int b = blockIdx.x;
    for (int idx = j; idx < LAT * LAT; idx += 128) As[idx] = g_Ap0[idx];
    float s = g_h0[b * LAT + j];
    for (int k = 0; k < NCHUNK; k++) {
        g_sk[(k * BATCH + b) * LAT + j] = s;
        sv[j] = s;
        __syncthreads();
        float acc = g_lend[(k * BATCH + b) * LAT + j];
#pragma unroll 8
        for (int m4 = 0; m4 < LAT; m4 += 4) {
            float a0 = As[(m4+0)*LAT + j], a1 = As[(m4+1)*LAT + j];
            float a2 = As[(m4+2)*LAT + j], a3 = As[(m4+3)*LAT + j];
            float4 h = *(const float4*)&sv[m4];
            acc = fmaf(h.x, a0, fmaf(h.y, a1, fmaf(h.z, a2, fmaf(h.w, a3, acc))));
        }
        __syncthreads();
        s = acc;
    }
}

// ---------------- launch ----------------
extern "C" void kernel_launch(void* const* d_in, const int* in_sizes, int n_in,
                              void* d_out, int out_size)
{
    const float* in  = (const float*)d_in[0];
    const float* ew0 = (const float*)d_in[1];
    const float* eb0 = (const float*)d_in[2];
    const float* ew1 = (const float*)d_in[3];
    const float* eb1 = (const float*)d_in[4];
    const float* ew2 = (const float*)d_in[5];
    const float* eb2 = (const float*)d_in[6];
    const float* gam = (const float*)d_in[7];
    const float* bet = (const float*)d_in[8];
    const float* Aw  = (const float*)d_in[9];
    const float* Bd  = (const float*)d_in[10];
    const float* dw0 = (const float*)d_in[11];
    const float* db0 = (const float*)d_in[12];
    const float* dw1 = (const float*)d_in[13];
    const float* db1 = (const float*)d_in[14];
    const float* dw2 = (const float*)d_in[15];
    const float* db2 = (const float*)d_in[16];
    float* out = (float*)d_out;

    u16 *a1, *a2, *z1;
    u16 *we0h, *we0l, *we1h, *we1l, *we2h, *we2l, *wd0h, *wd0l, *wd1h, *wd1l, *wd2h, *wd2l;
    cudaGetSymbolAddress((void**)&a1, g_a1);
    cudaGetSymbolAddress((void**)&a2, g_a2);
    cudaGetSymbolAddress((void**)&z1, g_z1);
    cudaGetSymbolAddress((void**)&we0h, g_we0h); cudaGetSymbolAddress((void**)&we0l, g_we0l);
    cudaGetSymbolAddress((void**)&we1h, g_we1h); cudaGetSymbolAddress((void**)&we1l, g_we1l);
    cudaGetSymbolAddress((void**)&we2h, g_we2h); cudaGetSymbolAddress((void**)&we2l, g_we2l);
    cudaGetSymbolAddress((void**)&wd0h, g_wd0h); cudaGetSymbolAddress((void**)&wd0l, g_wd0l);
    cudaGetSymbolAddress((void**)&wd1h, g_wd1h); cudaGetSymbolAddress((void**)&wd1l, g_wd1l);
    cudaGetSymbolAddress((void**)&wd2h, g_wd2h); cudaGetSymbolAddress((void**)&wd2l, g_wd2l);

    // smem: NT=128: 18432 + 2*18432 + 1536 = 56832 ; NT=64: 18432 + 2*9216 + 1536 = 38400
    const int SM128 = 56832;
    const int SM64  = 38400;

    cudaFuncSetAttribute(k_sq,    cudaFuncAttributeMaxDynamicSharedMemorySize, 65536);
    cudaFuncSetAttribute(k_pass,  cudaFuncAttributeMaxDynamicSharedMemorySize, 73728);
    cudaFuncSetAttribute(k_bound, cudaFuncAttributeMaxDynamicSharedMemorySize, 66560);
    cudaFuncSetAttribute(k_gemm<64,128,0,0>,  cudaFuncAttributeMaxDynamicSharedMemorySize, SM128);
    cudaFuncSetAttribute(k_gemm<256,128,0,1>, cudaFuncAttributeMaxDynamicSharedMemorySize, SM128);
    cudaFuncSetAttribute(k_gemm<256,128,1,1>, cudaFuncAttributeMaxDynamicSharedMemorySize, SM128);
    cudaFuncSetAttribute(k_gemm<128,128,0,1>, cudaFuncAttributeMaxDynamicSharedMemorySize, SM128);
    cudaFuncSetAttribute(k_gemm<256,64,2,1>,  cudaFuncAttributeMaxDynamicSharedMemorySize, SM64);

    static cudaStream_t sB = nullptr;
    static cudaEvent_t evF = nullptr, evB = nullptr;
    if (!sB) {
        cudaStreamCreateWithFlags(&sB, cudaStreamNonBlocking);
        cudaEventCreateWithFlags(&evF, cudaEventDisableTiming);
        cudaEventCreateWithFlags(&evB, cudaEventDisableTiming);
    }

    cudaEventRecord(evF, 0);

    // ---- stream 0: encoder ----
    k_init<<<1, 128>>>();
    k_prepw<<<(64*256+255)/256,  256>>>(ew0, 64, 256, 128, we0h, we0l);
    k_prepw<<<(256*256+255)/256, 256>>>(ew1, 256, 256, 128, we1h, we1l);
    k_prepw<<<(256*128+255)/256, 256>>>(ew2, 256, 128, 128, we2h, we2l);
    k_gemm<64,128,0,0><<<dim3(512,2), 256, SM128>>>(in, nullptr, IND,
        we0h, we0l, eb0, a1, nullptr, 256);
    k_gemm<256,128,0,1><<<dim3(512,2), 256, SM128>>>(nullptr, a1, 256,
        we1h, we1l, eb1, a2, nullptr, 256);
    k_gemm<256,128,1,1><<<dim3(512,1), 256, SM128>>>(nullptr, a2, 256,
        we2h, we2l, eb2, nullptr, nullptr, 0);
    k_fin<<<1, 128>>>(gam, bet);

    // ---- stream B: pass0 first (no deps), then A^32 chain, then dec preps ----
    cudaStreamWaitEvent(sB, evF, 0);
    k_pass<<<dim3(NCHUNK, NBS), 128, 73728, sB>>>(in, Aw, Bd, 0);
    for (int s = 0; s < 5; s++) k_sq<<<32, 512, 65536, sB>>>(Aw, s);
    k_prepw<<<(128*256+255)/256, 256, 0, sB>>>(dw0, 128, 256, 128, wd0h, wd0l);
    k_prepw<<<(256*256+255)/256, 256, 0, sB>>>(dw1, 256, 256, 128, wd1h, wd1l);
    k_prepw<<<(256*64+255)/256,  256, 0, sB>>>(dw2, 256, 64, 64, wd2h, wd2l);
    cudaEventRecord(evB, sB);

    // ---- join, serial tail ----
    cudaStreamWaitEvent(0, evB, 0);
    k_bound<<<BATCH, 128, 66560>>>();
    k_pass<<<dim3(NCHUNK, NBS), 128, 73728>>>(in, Aw, Bd, 1);
    k_gemm<128,128,0,1><<<dim3(512,2), 256, SM128>>>(nullptr, z1, 128,
        wd0h, wd0l, db0, a1, nullptr, 256);
    k_gemm<256,128,0,1><<<dim3(512,2), 256, SM128>>>(nullptr, a1, 256,
        wd1h, wd1l, db1, a2, nullptr, 256);
    k_gemm<256,64,2,1><<<dim3(512,1), 256, SM64>>>(nullptr, a2, 256,
        wd2h, wd2l, db2, nullptr, out, 64);
}

// round 12
// speedup vs baseline: 1.5569x; 1.1012x over previous
#include <cuda_runtime.h>
#include <cuda_fp16.h>
#include <cstdint>

typedef unsigned short u16;
typedef unsigned int u32;

#define BATCH 32
#define SEQ   2048
#define STATE 64
#define LAT   128
#define ENC   256
#define IND   320
#define NPOS  (BATCH*SEQ)
#define NCHUNK 64
#define CLEN   32
#define RPC    8
#define NBS    4

// ---------------- device scratch ----------------
__device__ float g_sum[LAT];
__device__ float g_sumsq[LAT];
__device__ float g_z0[BATCH*LAT];
__device__ float g_h0[BATCH*LAT];
__device__ float g_Ap0[LAT*LAT];
__device__ float g_Ap1[LAT*LAT];
__device__ float g_lend[NCHUNK*BATCH*LAT];
__device__ float g_sk[NCHUNK*BATCH*LAT];
// fp16 activations
__device__ u16 g_a1[(size_t)NPOS*ENC];
__device__ u16 g_a2[(size_t)NPOS*ENC];
__device__ u16 g_z1[(size_t)NPOS*LAT];
// packed fp16 weight images (chunk-blocked, 72-half padded rows, transposed [n][k])
__device__ __align__(16) u16 g_we0[256*1*72];
__device__ __align__(16) u16 g_we1[256*4*72];
__device__ __align__(16) u16 g_we2[128*4*72];
__device__ __align__(16) u16 g_wd0[256*2*72];
__device__ __align__(16) u16 g_wd1[256*4*72];
__device__ __align__(16) u16 g_wd2[64*4*72];

// ---------------- helpers ----------------
__device__ __forceinline__ u32 smem_u32(const void* p) {
    u32 a;
    asm("{ .reg .u64 t; cvta.to.shared.u64 t, %1; cvt.u32.u64 %0, t; }" : "=r"(a) : "l"(p));
    return a;
}
#define LDSM4(r, a) \
    asm volatile("ldmatrix.sync.aligned.m8n8.x4.shared.b16 {%0,%1,%2,%3}, [%4];" \
        : "=r"((r)[0]), "=r"((r)[1]), "=r"((r)[2]), "=r"((r)[3]) : "r"(a))
#define MMA(d, a, b) \
    asm volatile("mma.sync.aligned.m16n8k16.row.col.f32.f16.f16.f32 " \
        "{%0,%1,%2,%3},{%4,%5,%6,%7},{%8,%9},{%0,%1,%2,%3};" \
        : "+f"((d)[0]), "+f"((d)[1]), "+f"((d)[2]), "+f"((d)[3]) \
        : "r"((a)[0]), "r"((a)[1]), "r"((a)[2]), "r"((a)[3]), "r"((b)[0]), "r"((b)[1]))
#define CPA16(dst, src) asm volatile("cp.async.cg.shared.global [%0], [%1], 16;" :: "r"(dst), "l"(src))
#define CPA_FLUSH() asm volatile("cp.async.commit_group;\ncp.async.wait_group 0;" ::: "memory")

__device__ __forceinline__ u16 f2h(float v) { __half h = __float2half(v); return *(u16*)&h; }

// ---------------- small kernels ----------------
__global__ void k_init() {
    int t = threadIdx.x;
    if (t < LAT) { g_sum[t] = 0.f; g_sumsq[t] = 0.f; }
}

__global__ void k_sq(const float* __restrict__ Aw, int step) {
    extern __shared__ float S[];
    const float* src = (step == 0) ? Aw : ((step & 1) ? g_Ap0 : g_Ap1);
    float* dst = (step & 1) ? g_Ap1 : g_Ap0;
    int t = threadIdx.x;
    for (int i = t; i < LAT*LAT; i += 512) S[i] = src[i];
    __syncthreads();
    int base = blockIdx.x * 512 + t;
    int i = base >> 7, j = base & 127;
    float acc = 0.f;
#pragma unroll 8
    for (int k = 0; k < LAT; k++) acc = fmaf(S[i*LAT + k], S[k*LAT + j], acc);
    dst[base] = acc;
}

__global__ void k_prepw(const float* __restrict__ W, int K, int N, int NT,
                        u16* __restrict__ oh) {
    int idx = blockIdx.x * 256 + threadIdx.x;
    if (idx >= K * N) return;
    int k = idx / N, n = idx % N;
    int NCH = K >> 6;
    int nt = n / NT, nloc = n % NT, c = k >> 6, kl = k & 63;
    size_t d = ((size_t)(nt * NCH + c) * NT + nloc) * 72 + kl;
    oh[d] = f2h(W[idx]);
}

// ---------------- HMMA GEMM: pure fp16, single pass ----------------
// EPI 0: bias+relu -> fp16 out; EPI 1: BN stats + z0; EPI 2: bias -> fp32 out
// ASRC 0: A fp32 (convert on load); 1: A fp16 array
template<int K, int NT, int EPI, int ASRC>
__global__ void __launch_bounds__(256, 2) k_gemm(
    const float* __restrict__ A32, const u16* __restrict__ Ax, int lda,
    const u16* __restrict__ Wx,
    const float* __restrict__ bias,
    u16* __restrict__ Ox, float* __restrict__ outF, int ldo)
{
    constexpr int KC  = 64;
    constexpr int NCH = K / KC;
    constexpr int SMA = 128 * 144;
    constexpr int SMW = NT * 144;
    constexpr int SB  = SMA + SMW;
    constexpr int MT  = (NT == 128) ? 2 : 1;
    constexpr int WM  = (NT == 128) ? 4 : 8;

    extern __shared__ char sm[];
    u32 sb = smem_u32(sm);
    int tid = threadIdx.x, wid = tid >> 5, l = tid & 31;
    int wm = wid % WM, wn = wid / WM;
    int tile = blockIdx.x, nt = blockIdx.y, nt0 = nt * NT;
    int RW = wm * (MT * 16);

    float* sbias = (float*)(sm + SB);
    float* ssum  = (float*)(sm + SB + 512);
    float* ssq   = (float*)(sm + SB + 1024);
    if (tid < NT) sbias[tid] = bias[nt0 + tid];
    if (EPI == 1 && tid < 128) { ssum[tid] = 0.f; ssq[tid] = 0.f; }

    float acc[MT][8][4];
#pragma unroll
    for (int mt = 0; mt < MT; mt++)
#pragma unroll
        for (int n = 0; n < 8; n++)
#pragma unroll
            for (int i = 0; i < 4; i++) acc[mt][n][i] = 0.f;

    u32 aoff = (RW + (l & 15)) * 144 + (l >> 4) * 16;
    u32 boff = (wn*64 + (l & 7) + ((l >> 4) * 8)) * 144 + (((l >> 3) & 1) * 16);
    u32 sA = sb, sW = sb + SMA;

    for (int c = 0; c < NCH; c++) {
        __syncthreads();
        // W chunk
        {
            const u16* wp = Wx + (size_t)(nt * NCH + c) * NT * 72;
#pragma unroll
            for (int i = tid; i < NT * 9; i += 256)
                CPA16(sW + i*16, wp + i*8);
        }
        // A chunk
        if (ASRC == 1) {
#pragma unroll
            for (int i = tid; i < 1024; i += 256) {
                int row = i >> 3, seg = i & 7;
                size_t go = (size_t)(tile*128 + row) * lda + c*KC + seg*8;
                CPA16(sA + row*144 + seg*16, Ax + go);
            }
        } else {
            int r = tid & 127, kh = (tid >> 7) * 32;
            const float* ap = A32 + (size_t)(tile*128 + r) * lda + c*KC + kh;
#pragma unroll
            for (int j = 0; j < 4; j++) {
                float4 f0 = *(const float4*)(ap + j*8);
                float4 f1 = *(const float4*)(ap + j*8 + 4);
                float f[8] = {f0.x,f0.y,f0.z,f0.w,f1.x,f1.y,f1.z,f1.w};
                union { u16 us[8]; uint4 u; } ph;
#pragma unroll
                for (int q = 0; q < 8; q++) ph.us[q] = f2h(f[q]);
                *(uint4*)(sm + r*144 + (kh + j*8)*2) = ph.u;
            }
        }
        CPA_FLUSH();
        __syncthreads();
#pragma unroll
        for (int ks = 0; ks < 4; ks++) {
            int k2 = ks * 32;
            u32 af[MT][4], bf[4][4];
#pragma unroll
            for (int mt = 0; mt < MT; mt++) LDSM4(af[mt], sA + aoff + mt*2304 + k2);
#pragma unroll
            for (int p = 0; p < 4; p++)     LDSM4(bf[p], sW + boff + p*2304 + k2);
#pragma unroll
            for (int mt = 0; mt < MT; mt++)
#pragma unroll
                for (int p = 0; p < 4; p++) {
                    MMA(acc[mt][2*p],   af[mt], bf[p]);
                    MMA(acc[mt][2*p+1], af[mt], &bf[p][2]);
                }
        }
    }

    int g = l >> 2, tg = l & 3;
#pragma unroll
    for (int mt = 0; mt < MT; mt++) {
        int row = tile*128 + RW + mt*16 + g;
#pragma unroll
        for (int n = 0; n < 8; n++) {
            int colL = wn*64 + n*8 + tg*2;
            float b0 = sbias[colL], b1 = sbias[colL + 1];
            float v0 = acc[mt][n][0] + b0, v1 = acc[mt][n][1] + b1;
            float v2 = acc[mt][n][2] + b0, v3 = acc[mt][n][3] + b1;
            if (EPI != 2) {
                v0 = fmaxf(v0, 0.f); v1 = fmaxf(v1, 0.f);
                v2 = fmaxf(v2, 0.f); v3 = fmaxf(v3, 0.f);
            }
            if (EPI == 1) {
                atomicAdd(&ssum[colL],     v0 + v2);
                atomicAdd(&ssq[colL],      v0*v0 + v2*v2);
                atomicAdd(&ssum[colL + 1], v1 + v3);
                atomicAdd(&ssq[colL + 1],  v1*v1 + v3*v3);
                if (((tile & 15) == 0) && g == 0 && wm == 0 && mt == 0) {
                    g_z0[(tile >> 4) * LAT + colL]     = v0;
                    g_z0[(tile >> 4) * LAT + colL + 1] = v1;
                }
            } else if (EPI == 0) {
                size_t o0 = (size_t)row * ldo + nt0 + colL;
                size_t o1 = (size_t)(row + 8) * ldo + nt0 + colL;
                *(u32*)&Ox[o0] = (u32)f2h(v0) | ((u32)f2h(v1) << 16);
                *(u32*)&Ox[o1] = (u32)f2h(v2) | ((u32)f2h(v3) << 16);
            } else {
                *(float2*)&outF[(size_t)row * ldo + nt0 + colL]       = make_float2(v0, v1);
                *(float2*)&outF[(size_t)(row + 8) * ldo + nt0 + colL] = make_float2(v2, v3);
            }
        }
    }
    if (EPI == 1) {
        __syncthreads();
        if (tid < 128) {
            atomicAdd(&g_sum[tid],   ssum[tid]);
            atomicAdd(&g_sumsq[tid], ssq[tid]);
        }
    }
}

// ---------------- BN finalize ----------------
__global__ void k_fin(const float* __restrict__ gamma, const float* __restrict__ beta)
{
    int j = threadIdx.x;
    float inv = 1.f / (float)NPOS;
    float m  = g_sum[j] * inv;
    float v  = g_sumsq[j] * inv - m * m;
    float rs = rsqrtf(v + 1e-5f);
    float ga = gamma[j], be = beta[j];
    for (int b = 0; b < BATCH; b++) {
        float z = g_z0[b*LAT + j];
        g_h0[b*LAT + j] = (z - m) * rs * ga + be;
    }
}

// ---------------- chunked scan ----------------
__global__ void __launch_bounds__(128) k_pass(const float* __restrict__ in,
                                              const float* __restrict__ Aw,
                                              const float* __restrict__ Bd, int pass)
{
    extern __shared__ float smf[];
    float* As = smf;
    float* hs = smf + LAT * LAT;
    int j     = threadIdx.x;
    int chunk = blockIdx.x;
    int b0r   = blockIdx.y * RPC;

    for (int idx = j; idx < LAT * LAT; idx += 128) As[idx] = Aw[idx];
    float dj = fminf(fmaxf(Bd[j], -0.95f), 0.95f);
#pragma unroll
    for (int i = 0; i < RPC; i++) {
        float v = (pass == 0) ? 0.f : g_sk[(chunk * BATCH + (b0r + i)) * LAT + j];
        hs[i * LAT + j] = v;
    }
    __syncthreads();

    int t0 = chunk * CLEN;
    int buf = 0;
    for (int t = t0; t < t0 + CLEN; t++) {
        float acc[RPC];
#pragma unroll
        for (int i = 0; i < RPC; i++)
            acc[i] = in[((long)(b0r + i) * SEQ + t) * IND + (STATE + LAT) + j] * dj;

        const float* hb = hs + buf * (RPC * LAT);
#pragma unroll 8
        for (int k4 = 0; k4 < LAT; k4 += 4) {
            float a0 = As[(k4+0)*LAT + j], a1 = As[(k4+1)*LAT + j];
            float a2 = As[(k4+2)*LAT + j], a3 = As[(k4+3)*LAT + j];
#pragma unroll
            for (int i = 0; i < RPC; i++) {
                float4 h = *(const float4*)&hb[i * LAT + k4];
                acc[i] = fmaf(h.x, a0, fmaf(h.y, a1, fmaf(h.z, a2, fmaf(h.w, a3, acc[i]))));
            }
        }
        buf ^= 1;
        float* hn = hs + buf * (RPC * LAT);
#pragma unroll
        for (int i = 0; i < RPC; i++) hn[i * LAT + j] = acc[i];
        if (pass == 1) {
#pragma unroll
            for (int i = 0; i < RPC; i++) {
                size_t pos = (size_t)(b0r + i) * SEQ + t;
                g_z1[pos * LAT + j] = f2h(acc[i]);
            }
        }
        __syncthreads();
    }
    if (pass == 0) {
#pragma unroll
        for (int i = 0; i < RPC; i++)
            g_lend[(chunk * BATCH + (b0r + i)) * LAT + j] = hs[buf * (RPC * LAT) + i * LAT + j];
    }
}

// ---------------- boundary scan via A^32 ----------------
__global__ void __launch_bounds__(128) k_bound()
{
    extern __shared__ float smf[];
    float* As = smf;
    float* sv = smf + LAT * LAT;
    int j = threadIdx.x;
    int b = blockIdx.x;
    for (int idx = j; idx < LAT * LAT; idx += 128) As[idx] = g_Ap0[idx];
    float s = g_h0[b * LAT + j];
    for (int k = 0; k < NCHUNK; k++) {
        g_sk[(k * BATCH + b) * LAT + j] = s;
        sv[j] = s;
        __syncthreads();
        float acc = g_lend[(k * BATCH + b) * LAT + j];
#pragma unroll 8
        for (int m4 = 0; m4 < LAT; m4 += 4) {
            float a0 = As[(m4+0)*LAT + j], a1 = As[(m4+1)*LAT + j];
            float a2 = As[(m4+2)*LAT + j], a3 = As[(m4+3)*LAT + j];
            float4 h = *(const float4*)&sv[m4];
            acc = fmaf(h.x, a0, fmaf(h.y, a1, fmaf(h.z, a2, fmaf(h.w, a3, acc))));
        }
        __syncthreads();
        s = acc;
    }
}

// ---------------- launch ----------------
extern "C" void kernel_launch(void* const* d_in, const int* in_sizes, int n_in,
                              void* d_out, int out_size)
{
    const float* in  = (const float*)d_in[0];
    const float* ew0 = (const float*)d_in[1];
    const float* eb0 = (const float*)d_in[2];
    const float* ew1 = (const float*)d_in[3];
    const float* eb1 = (const float*)d_in[4];
    const float* ew2 = (const float*)d_in[5];
    const float* eb2 = (const float*)d_in[6];
    const float* gam = (const float*)d_in[7];
    const float* bet = (const float*)d_in[8];
    const float* Aw  = (const float*)d_in[9];
    const float* Bd  = (const float*)d_in[10];
    const float* dw0 = (const float*)d_in[11];
    const float* db0 = (const float*)d_in[12];
    const float* dw1 = (const float*)d_in[13];
    const float* db1 = (const float*)d_in[14];
    const float* dw2 = (const float*)d_in[15];
    const float* db2 = (const float*)d_in[16];
    float* out = (float*)d_out;

    u16 *a1, *a2, *z1, *we0, *we1, *we2, *wd0, *wd1, *wd2;
    cudaGetSymbolAddress((void**)&a1, g_a1);
    cudaGetSymbolAddress((void**)&a2, g_a2);
    cudaGetSymbolAddress((void**)&z1, g_z1);
    cudaGetSymbolAddress((void**)&we0, g_we0);
    cudaGetSymbolAddress((void**)&we1, g_we1);
    cudaGetSymbolAddress((void**)&we2, g_we2);
    cudaGetSymbolAddress((void**)&wd0, g_wd0);
    cudaGetSymbolAddress((void**)&wd1, g_wd1);
    cudaGetSymbolAddress((void**)&wd2, g_wd2);

    // smem: NT=128: 18432 + 18432 + 1536 = 38400 ; NT=64: 18432 + 9216 + 1536 = 29184
    const int SM128 = 38400;
    const int SM64  = 29184;

    cudaFuncSetAttribute(k_sq,    cudaFuncAttributeMaxDynamicSharedMemorySize, 65536);
    cudaFuncSetAttribute(k_pass,  cudaFuncAttributeMaxDynamicSharedMemorySize, 73728);
    cudaFuncSetAttribute(k_bound, cudaFuncAttributeMaxDynamicSharedMemorySize, 66560);
    cudaFuncSetAttribute(k_gemm<64,128,0,0>,  cudaFuncAttributeMaxDynamicSharedMemorySize, SM128);
    cudaFuncSetAttribute(k_gemm<256,128,0,1>, cudaFuncAttributeMaxDynamicSharedMemorySize, SM128);
    cudaFuncSetAttribute(k_gemm<256,128,1,1>, cudaFuncAttributeMaxDynamicSharedMemorySize, SM128);
    cudaFuncSetAttribute(k_gemm<128,128,0,1>, cudaFuncAttributeMaxDynamicSharedMemorySize, SM128);
    cudaFuncSetAttribute(k_gemm<256,64,2,1>,  cudaFuncAttributeMaxDynamicSharedMemorySize, SM64);

    static cudaStream_t sB = nullptr;
    static cudaEvent_t evF = nullptr, evB = nullptr;
    if (!sB) {
        cudaStreamCreateWithFlags(&sB, cudaStreamNonBlocking);
        cudaEventCreateWithFlags(&evF, cudaEventDisableTiming);
        cudaEventCreateWithFlags(&evB, cudaEventDisableTiming);
    }

    cudaEventRecord(evF, 0);

    // ---- stream 0: encoder ----
    k_init<<<1, 128>>>();
    k_prepw<<<(64*256+255)/256,  256>>>(ew0, 64, 256, 128, we0);
    k_prepw<<<(256*256+255)/256, 256>>>(ew1, 256, 256, 128, we1);
    k_prepw<<<(256*128+255)/256, 256>>>(ew2, 256, 128, 128, we2);
    k_gemm<64,128,0,0><<<dim3(512,2), 256, SM128>>>(in, nullptr, IND,
        we0, eb0, a1, nullptr, 256);
    k_gemm<256,128,0,1><<<dim3(512,2), 256, SM128>>>(nullptr, a1, 256,
        we1, eb1, a2, nullptr, 256);
    k_gemm<256,128,1,1><<<dim3(512,1), 256, SM128>>>(nullptr, a2, 256,
        we2, eb2, nullptr, nullptr, 0);
    k_fin<<<1, 128>>>(gam, bet);

    // ---- stream B: pass0 first (no deps), then A^32 chain, then dec preps ----
    cudaStreamWaitEvent(sB, evF, 0);
    k_pass<<<dim3(NCHUNK, NBS), 128, 73728, sB>>>(in, Aw, Bd, 0);
    for (int s = 0; s < 5; s++) k_sq<<<32, 512, 65536, sB>>>(Aw, s);
    k_prepw<<<(128*256+255)/256, 256, 0, sB>>>(dw0, 128, 256, 128, wd0);
    k_prepw<<<(256*256+255)/256, 256, 0, sB>>>(dw1, 256, 256, 128, wd1);
    k_prepw<<<(256*64+255)/256,  256, 0, sB>>>(dw2, 256, 64, 64, wd2);
    cudaEventRecord(evB, sB);

    // ---- join, serial tail ----
    cudaStreamWaitEvent(0, evB, 0);
    k_bound<<<BATCH, 128, 66560>>>();
    k_pass<<<dim3(NCHUNK, NBS), 128, 73728>>>(in, Aw, Bd, 1);
    k_gemm<128,128,0,1><<<dim3(512,2), 256, SM128>>>(nullptr, z1, 128,
        wd0, db0, a1, nullptr, 256);
    k_gemm<256,128,0,1><<<dim3(512,2), 256, SM128>>>(nullptr, a1, 256,
        wd1, db1, a2, nullptr, 256);
    k_gemm<256,64,2,1><<<dim3(512,1), 256, SM64>>>(nullptr, a2, 256,
        wd2, db2, nullptr, out, 64);
}